// round 17
// baseline (speedup 1.0000x reference)
#include <cuda_runtime.h>
#include <cuda_bf16.h>
#include <cuda_fp16.h>
#include <cstdint>

#define NB 1024
#define NV 64
#define NI 256
#define NO 256
constexpr float EPS = 1e-5f;

// ---------------------------------------------------------------------------
// Device scratch
// ---------------------------------------------------------------------------
__device__ __half g_h16[(size_t)NB * NV * NO];   // 32 MB: h (fp16)
__device__ __half g_W16[(size_t)NV * NI * NO];   // 8 MB, NATURAL layout [v][i][o]
__device__ __half g_adj16[NV * NV];
__device__ float g_sum[NV * NO];
__device__ float g_sqs[NV * NO];
__device__ float g_s[NV * NO];
__device__ float g_t[NV * NO];

// ---------------------------------------------------------------------------
// Helpers (baseline PTX only)
// ---------------------------------------------------------------------------
__device__ __forceinline__ uint32_t smem_u32(const void* p) {
    uint32_t a;
    asm("{ .reg .u64 t; cvta.to.shared.u64 t, %1; cvt.u32.u64 %0, t; }"
        : "=r"(a) : "l"(p));
    return a;
}
#define SWZ(off) ((uint32_t)(off) ^ ((((uint32_t)(off)) >> 3) & 0x70))  // 128B rows

__device__ __forceinline__ void ldsm_x4(uint32_t* r, uint32_t addr) {
    asm volatile("ldmatrix.sync.aligned.m8n8.x4.shared.b16 {%0,%1,%2,%3}, [%4];"
                 : "=r"(r[0]), "=r"(r[1]), "=r"(r[2]), "=r"(r[3]) : "r"(addr));
}
__device__ __forceinline__ void ldsm_x2t(uint32_t* r, uint32_t addr) {
    asm volatile("ldmatrix.sync.aligned.m8n8.x2.trans.shared.b16 {%0,%1}, [%2];"
                 : "=r"(r[0]), "=r"(r[1]) : "r"(addr));
}
__device__ __forceinline__ void mma_f16(float* d, const uint32_t* a,
                                        const uint32_t* b) {
    asm volatile(
        "mma.sync.aligned.m16n8k16.row.col.f32.f16.f16.f32 "
        "{%0,%1,%2,%3}, {%4,%5,%6,%7}, {%8,%9}, {%0,%1,%2,%3};"
        : "+f"(d[0]), "+f"(d[1]), "+f"(d[2]), "+f"(d[3])
        : "r"(a[0]), "r"(a[1]), "r"(a[2]), "r"(a[3]), "r"(b[0]), "r"(b[1]));
}
__device__ __forceinline__ void cp16(uint32_t smem, const void* g) {
    asm volatile("cp.async.cg.shared.global [%0], [%1], 16;"
                 :: "r"(smem), "l"(g) : "memory");
}
#define CP_COMMIT() asm volatile("cp.async.commit_group;" ::: "memory")
#define CP_WAIT(N)  asm volatile("cp.async.wait_group %0;" :: "n"(N) : "memory")

// ---------------------------------------------------------------------------
// Kernel A: W -> fp16, NATURAL layout (pure cast, coalesced). grid 4096 x 256.
// ---------------------------------------------------------------------------
__global__ __launch_bounds__(256) void convert_W(const float* __restrict__ W) {
    size_t i4 = (size_t)blockIdx.x * 256 + threadIdx.x;  // float4 index
    float4 x = ((const float4*)W)[i4];
    __half2 p0 = __floats2half2_rn(x.x, x.y);
    __half2 p1 = __floats2half2_rn(x.z, x.w);
    ((uint2*)g_W16)[i4] = make_uint2(*(uint32_t*)&p0, *(uint32_t*)&p1);
}

// ---------------------------------------------------------------------------
// Kernel A2: adj -> fp16 AND zero stats accumulators. grid 16 x 256.
// ---------------------------------------------------------------------------
__global__ void convert_adj(const float* __restrict__ adj) {
    int i = blockIdx.x * 256 + threadIdx.x;   // 0..4095
    g_adj16[i] = __float2half_rn(adj[i]);
    ((float4*)g_sum)[i] = make_float4(0.f, 0.f, 0.f, 0.f);
    ((float4*)g_sqs)[i] = make_float4(0.f, 0.f, 0.f, 0.f);
}

// ---------------------------------------------------------------------------
// Kernel B: pure-fp16 GEMM, FULL-WIDTH tile 128x256, 512 threads (16 warps),
// 2-stage double buffer, ONE sync per K-chunk. A staged once per (m,v).
// grid (NB/128, NV). Stage: A 16KB (SW128) + B 64 x 528B = 50176 B; x2 -> 1 CTA.
// ---------------------------------------------------------------------------
static constexpr int A_OFF = 0;
static constexpr int B_OFF = 16384;
static constexpr int BPITCH = 528;         // 512B row + 16B shift (conflict-free)
static constexpr int STG = 16384 + 64 * BPITCH;    // 50176
static constexpr int GEMM_DSMEM = 2 * STG + 1024;

__device__ __forceinline__ void load_A_regs(float4* areg,
                                            const float* __restrict__ feat,
                                            int m0, int v, int k0, int t) {
#pragma unroll
    for (int r = 0; r < 4; r++) {
        int idx = t + r * 512;            // 0..2047 float4s (128m x 64k)
        int m = idx >> 4, kq = idx & 15;
        areg[r] = *(const float4*)(feat +
                   ((size_t)(m0 + m) * NV + v) * NI + k0 + kq * 4);
    }
}
__device__ __forceinline__ void store_A_smem(char* buf, const float4* areg,
                                             int t) {
#pragma unroll
    for (int r = 0; r < 4; r++) {
        int idx = t + r * 512;
        int m = idx >> 4, kq = idx & 15;
        float4 x = areg[r];
        __half2 p0 = __floats2half2_rn(x.x, x.y);
        __half2 p1 = __floats2half2_rn(x.z, x.w);
        uint32_t off = SWZ(m * 128 + kq * 8);
        *(uint2*)(buf + A_OFF + off) =
            make_uint2(*(uint32_t*)&p0, *(uint32_t*)&p1);
    }
}
// B tile: 64 k-rows x 256 n-cols fp16, natural row-major [k][n], pitch 528B.
__device__ __forceinline__ void issue_B(uint32_t sb,
                                        const __half* __restrict__ Wp,
                                        int k0, int t) {
#pragma unroll
    for (int r = 0; r < 4; r++) {
        int idx = t + r * 512;            // 0..2047: 64 rows x 32 chunks
        int k = idx >> 5, c16 = idx & 31;
        cp16(sb + B_OFF + k * BPITCH + c16 * 16,
             Wp + (size_t)(k0 + k) * NO + c16 * 8);
    }
}

__global__ __launch_bounds__(512, 1) void gemm_mma(const float* __restrict__ feat,
                                                   const float* __restrict__ bias) {
    extern __shared__ char dynraw[];
    uint32_t rawa = smem_u32(dynraw);
    char* smb = dynraw + (((rawa + 1023) & ~1023u) - rawa);
    const uint32_t sb0 = smem_u32(smb);

    const int v  = blockIdx.y;
    const int m0 = blockIdx.x * 128;
    const int t  = threadIdx.x;
    const int lane = t & 31;
    const int w = t >> 5;                 // 0..15
    const int mw = (w >> 3) * 64;         // 2 m-groups
    const int nw = (w & 7) * 32;          // 8 n-groups covering 256

    float acc[4][4][4];
#pragma unroll
    for (int i = 0; i < 4; i++)
#pragma unroll
        for (int j = 0; j < 4; j++)
#pragma unroll
            for (int q = 0; q < 4; q++) acc[i][j][q] = 0.f;

    const __half* Wp = g_W16 + (size_t)v * NI * NO;   // full-width rows

    // ---- prologue: stage0 gets chunk0; A1 in regs
    float4 areg[4];
    load_A_regs(areg, feat, m0, v, 0, t);
    issue_B(sb0, Wp, 0, t);
    CP_COMMIT();                               // group: B0
    store_A_smem(smb, areg, t);
    load_A_regs(areg, feat, m0, v, 64, t);     // A1 -> regs

#pragma unroll
    for (int c = 0; c < 4; c++) {
        const uint32_t sb = sb0 + (c & 1) * STG;

        CP_WAIT(0);            // B_c landed (only outstanding group)
        __syncthreads();       // B_c visible; free stage = consumers of c-1 done

        if (c < 3) {
            char* nbuf = smb + ((c + 1) & 1) * STG;
            store_A_smem(nbuf, areg, t);                   // A(c+1)
            if (c < 2) load_A_regs(areg, feat, m0, v, (c + 2) * 64, t);
            issue_B(sb0 + ((c + 1) & 1) * STG, Wp, (c + 1) * 64, t);
            CP_COMMIT();                                   // B(c+1), hidden
        }

        // ---- compute chunk c (4 k-steps of 16)
#pragma unroll
        for (int ks = 0; ks < 4; ks++) {
            uint32_t bh[4][2];
            uint32_t brow = sb + B_OFF + (ks * 16 + (lane & 15)) * BPITCH;
#pragma unroll
            for (int nt = 0; nt < 4; nt++) {
                ldsm_x2t(bh[nt], brow + (nw + nt * 8) * 2);
            }
            int arow = mw + (lane & 7) + ((lane >> 3) & 1) * 8;
            int ak = ks * 16 + ((lane >> 4) & 1) * 8;
#pragma unroll
            for (int mt = 0; mt < 4; mt++) {
                uint32_t ra[4];
                ldsm_x4(ra, sb + A_OFF + SWZ((arow + mt * 16) * 128 + ak * 2));
#pragma unroll
                for (int nt = 0; nt < 4; nt++) {
                    mma_f16(acc[mt][nt], ra, bh[nt]);
                }
            }
        }
    }

    // ---- epilogue: bias + store h (fp16) + shuffle-reduced column stats
#pragma unroll
    for (int nt = 0; nt < 4; nt++) {
        const int n = nw + nt * 8 + (lane & 3) * 2;    // global col (tile = full)
        float2 bv = *(const float2*)(bias + v * NO + n);
        float2 sum2 = make_float2(0.f, 0.f), sq2 = make_float2(0.f, 0.f);
#pragma unroll
        for (int mt = 0; mt < 4; mt++) {
            int mlo = m0 + mw + mt * 16 + (lane >> 2);
            float2 o0, o1;
            o0.x = acc[mt][nt][0] + bv.x;
            o0.y = acc[mt][nt][1] + bv.y;
            o1.x = acc[mt][nt][2] + bv.x;
            o1.y = acc[mt][nt][3] + bv.y;
            __half2 p0 = __floats2half2_rn(o0.x, o0.y);
            __half2 p1 = __floats2half2_rn(o1.x, o1.y);
            *(uint32_t*)(g_h16 + (size_t)mlo * (NV * NO) + v * NO + n) =
                *(uint32_t*)&p0;
            *(uint32_t*)(g_h16 + (size_t)(mlo + 8) * (NV * NO) + v * NO + n) =
                *(uint32_t*)&p1;
            sum2.x += o0.x + o1.x;
            sum2.y += o0.y + o1.y;
            sq2.x += fmaf(o0.x, o0.x, o1.x * o1.x);
            sq2.y += fmaf(o0.y, o0.y, o1.y * o1.y);
        }
#pragma unroll
        for (int msk = 4; msk <= 16; msk <<= 1) {
            sum2.x += __shfl_xor_sync(0xffffffffu, sum2.x, msk);
            sum2.y += __shfl_xor_sync(0xffffffffu, sum2.y, msk);
            sq2.x  += __shfl_xor_sync(0xffffffffu, sq2.x, msk);
            sq2.y  += __shfl_xor_sync(0xffffffffu, sq2.y, msk);
        }
        if (lane < 4) {
            atomicAdd(&g_sum[v * NO + n],     sum2.x);
            atomicAdd(&g_sum[v * NO + n + 1], sum2.y);
            atomicAdd(&g_sqs[v * NO + n],     sq2.x);
            atomicAdd(&g_sqs[v * NO + n + 1], sq2.y);
        }
    }
}

// ---------------------------------------------------------------------------
// Kernel C: finalize BN fold
// ---------------------------------------------------------------------------
__global__ __launch_bounds__(256) void stats_fin(const float* __restrict__ gamma,
                                                 const float* __restrict__ beta) {
    const int col = blockIdx.x * 256 + threadIdx.x;
    float mean = g_sum[col] * (1.f / NB);
    float var  = g_sqs[col] * (1.f / NB) - mean * mean;
    float s    = gamma[col] * rsqrtf(var + EPS);
    g_s[col] = s;
    g_t[col] = fmaf(-mean, s, beta[col]);
}

// ---------------------------------------------------------------------------
// Kernel D: tensorized mix, 1-term fp16 (unchanged; at memory floor ~15us)
// ---------------------------------------------------------------------------
static constexpr int OPAD = 264;                 // hs row stride (fp16 elems)
static constexpr int HS_OFF = 0;                 // 64*264*2 = 33792 B
static constexpr int ADJ_OFF = 33792;            // 64 rows x 72 elems x 2B
static constexpr int MIX_DSMEM = 43008 + 1024;

__global__ __launch_bounds__(256, 2) void mix_tc(float* __restrict__ out) {
    extern __shared__ char dynraw[];
    uint32_t rawa = smem_u32(dynraw);
    char* smb = dynraw + (((rawa + 1023) & ~1023u) - rawa);
    const uint32_t sbase = smem_u32(smb);

    const int b = blockIdx.x;
    const int t = threadIdx.x;
    const int lane = t & 31;
    const int w = t >> 5;

    // ---- stage hs = s*h + t (from fp16 h), single fp16, [v][OPAD]
    const uint2*  h2 = (const uint2*)(g_h16 + (size_t)b * NV * NO);  // 4 halves
    const float4* s4 = (const float4*)g_s;
    const float4* t4 = (const float4*)g_t;
#pragma unroll
    for (int r = 0; r < 16; r++) {
        int idx = t + r * 256;            // 0..4095 (4 elems each)
        int v = idx >> 6, oq = idx & 63;
        uint2 hp = h2[idx];
        __half2 ha = *(__half2*)&hp.x, hb = *(__half2*)&hp.y;
        float4 sv = s4[idx], tv = t4[idx];
        __half2 p0 = __floats2half2_rn(fmaf(__half2float(ha.x), sv.x, tv.x),
                                       fmaf(__half2float(ha.y), sv.y, tv.y));
        __half2 p1 = __floats2half2_rn(fmaf(__half2float(hb.x), sv.z, tv.z),
                                       fmaf(__half2float(hb.y), sv.w, tv.w));
        uint32_t off = (uint32_t)(v * (OPAD * 2) + oq * 8);
        *(uint2*)(smb + HS_OFF + off) =
            make_uint2(*(uint32_t*)&p0, *(uint32_t*)&p1);
    }
    // ---- stage adj (single fp16), [u][72] rows
#pragma unroll
    for (int r = 0; r < 8; r++) {
        int idx = t + r * 256;            // 0..2047 uint32s (2 fp16 each)
        int u = idx >> 5, q = idx & 31;
        *(uint32_t*)(smb + ADJ_OFF + u * 144 + q * 4) =
            ((const uint32_t*)g_adj16)[idx];
    }
    __syncthreads();

    const int mw = (w >> 1) * 16;     // u tile (4 tiles of 16)
    const int nw = (w & 1) * 128;     // o half

    float acc[16][4];
#pragma unroll
    for (int i = 0; i < 16; i++)
#pragma unroll
        for (int q = 0; q < 4; q++) acc[i][q] = 0.f;

#pragma unroll
    for (int ks = 0; ks < 4; ks++) {
        uint32_t ah[4];
        uint32_t aaddr = sbase + ADJ_OFF + (mw + (lane & 15)) * 144 +
                         (ks * 16 + (lane >> 4) * 8) * 2;
        ldsm_x4(ah, aaddr);

        uint32_t brow = sbase + HS_OFF + (ks * 16 + (lane & 15)) * (OPAD * 2);
#pragma unroll
        for (int nt = 0; nt < 16; nt++) {
            uint32_t bh[2];
            ldsm_x2t(bh, brow + (nw + nt * 8) * 2);
            mma_f16(acc[nt], ah, bh);
        }
    }

    // ---- epilogue: relu + store
    float* ob = out + (size_t)b * NV * NO;
    const int u0 = mw + (lane >> 2);
#pragma unroll
    for (int nt = 0; nt < 16; nt++) {
        int o = nw + nt * 8 + (lane & 3) * 2;
        float2 r0, r1;
        r0.x = fmaxf(acc[nt][0], 0.f);
        r0.y = fmaxf(acc[nt][1], 0.f);
        r1.x = fmaxf(acc[nt][2], 0.f);
        r1.y = fmaxf(acc[nt][3], 0.f);
        *(float2*)(ob + (size_t)u0 * NO + o) = r0;
        *(float2*)(ob + (size_t)(u0 + 8) * NO + o) = r1;
    }
}

// ---------------------------------------------------------------------------
extern "C" void kernel_launch(void* const* d_in, const int* in_sizes, int n_in,
                              void* d_out, int out_size) {
    const float* feat  = (const float*)d_in[0];
    const float* adj   = (const float*)d_in[1];
    const float* W     = (const float*)d_in[2];
    const float* bias  = (const float*)d_in[3];
    const float* gamma = (const float*)d_in[4];
    const float* beta  = (const float*)d_in[5];
    float* out = (float*)d_out;

    cudaFuncSetAttribute(gemm_mma, cudaFuncAttributeMaxDynamicSharedMemorySize,
                         GEMM_DSMEM);
    cudaFuncSetAttribute(mix_tc, cudaFuncAttributeMaxDynamicSharedMemorySize,
                         MIX_DSMEM);

    convert_W<<<4096, 256>>>(W);     // NV*NI*NO/4 float4s / 256
    convert_adj<<<16, 256>>>(adj);   // also zeroes g_sum/g_sqs
    gemm_mma<<<dim3(NB / 128, NV), 512, GEMM_DSMEM>>>(feat, bias);
    stats_fin<<<64, 256>>>(gamma, beta);
    mix_tc<<<NB, 256, MIX_DSMEM>>>(out);
}